// round 3
// baseline (speedup 1.0000x reference)
#include <cuda_runtime.h>
#include <cstddef>
#include <cstdint>

// Problem constants
#define Bn 64
#define Cn 128
#define Hn 256
#define Ln 1024
#define Gn 1024                    // 4*H
#define WSTRIDE 395264             // 4*H*(C+H+2)
#define S0OFF 131072               // G*C
#define S1OFF 393216               // S0 + G*H

// Scratch (device-global; no runtime allocation allowed)
__device__ float g_xg[(size_t)Bn * Ln * Gn];   // [b][l][g]  268 MB
__device__ float g_wt[(size_t)Bn * Hn * Gn];   // [b][k][g]   67 MB

// ---------------------------------------------------------------------------
// Fast nonlinearities (tanh.approx: abs err ~1e-5, far below 1e-3 tolerance)
// ---------------------------------------------------------------------------
__device__ __forceinline__ float fast_tanh(float x) {
    float r;
    asm("tanh.approx.f32 %0, %1;" : "=f"(r) : "f"(x));
    return r;
}
__device__ __forceinline__ float fast_sigmoid(float x) {
    // sigmoid(x) = 0.5 * tanh(0.5x) + 0.5
    return fmaf(fast_tanh(0.5f * x), 0.5f, 0.5f);
}

// ---------------------------------------------------------------------------
// Kernel 1: transpose W_hh[b][g][k] -> W_t[b][k][g] so the scan's weight
// loads are coalesced across gates. 32x32 smem tiles, both sides coalesced.
// ---------------------------------------------------------------------------
__global__ void __launch_bounds__(256) transpose_whh_kernel(const float* __restrict__ w) {
    __shared__ float tile[32][33];
    const int b  = blockIdx.z;
    const int k0 = blockIdx.x * 32;   // 256/32 = 8 tiles
    const int g0 = blockIdx.y * 32;   // 1024/32 = 32 tiles
    const int tx = threadIdx.x;       // 32
    const int ty = threadIdx.y;       // 8

    const float* src = w + (size_t)b * WSTRIDE + S0OFF;   // W_hh rows, stride H
#pragma unroll
    for (int i = 0; i < 4; i++) {
        int g = g0 + ty + i * 8;
        tile[ty + i * 8][tx] = src[(size_t)g * Hn + k0 + tx];
    }
    __syncthreads();
    float* dst = g_wt + (size_t)b * (Hn * (size_t)Gn);
#pragma unroll
    for (int i = 0; i < 4; i++) {
        int k = k0 + ty + i * 8;
        dst[(size_t)k * Gn + g0 + tx] = tile[tx][ty + i * 8];
    }
}

// ---------------------------------------------------------------------------
// Kernel 2: xg[b][l][g] = sum_c x[b][c][l] * W_ih[b][g][c] + bias1[g]+bias2[g]
// Tiled fp32 GEMM: 64(l) x 128(g) tile per CTA, K=C=128 in chunks of 16.
// 256 threads, 4x8 outputs per thread.
// ---------------------------------------------------------------------------
#define TL 64
#define TG 128
#define TC 16

__global__ void __launch_bounds__(256) gemm_xg_kernel(const float* __restrict__ x,
                                                      const float* __restrict__ w) {
    __shared__ float xs[TC][TL];         // [c][l]
    __shared__ float ws[TC][TG + 8];     // [c][g], padded

    const int b   = blockIdx.z;
    const int l0  = blockIdx.y * TL;
    const int g0  = blockIdx.x * TG;
    const int tid = threadIdx.x;
    const int tx  = tid & 15;            // g dimension (16)
    const int ty  = tid >> 4;            // l dimension (16)

    const float* xb = x + (size_t)b * (Cn * (size_t)Ln);
    const float* wb = w + (size_t)b * WSTRIDE;

    float acc[4][8];
#pragma unroll
    for (int i = 0; i < 4; i++)
#pragma unroll
        for (int j = 0; j < 8; j++) acc[i][j] = 0.f;

    const int xr = tid >> 4;             // c row for x-tile load
    const int xc = (tid & 15) * 4;       // l col

    for (int c0 = 0; c0 < Cn; c0 += TC) {
        // load x tile: 16 c-rows x 64 l, fully coalesced (l contiguous)
        float4 xv = *(const float4*)(xb + (size_t)(c0 + xr) * Ln + l0 + xc);
        *(float4*)&xs[xr][xc] = xv;
        // load W_ih tile: 128 g-rows x 16 c, transposed into [c][g]
#pragma unroll
        for (int it = 0; it < 2; it++) {
            int fi = tid + it * 256;           // 0..511 float4 index
            int g  = fi >> 2;
            int cq = (fi & 3) * 4;
            float4 wv = *(const float4*)(wb + (size_t)(g0 + g) * Cn + c0 + cq);
            ws[cq + 0][g] = wv.x;
            ws[cq + 1][g] = wv.y;
            ws[cq + 2][g] = wv.z;
            ws[cq + 3][g] = wv.w;
        }
        __syncthreads();
#pragma unroll
        for (int cc = 0; cc < TC; cc++) {
            float4 av = *(const float4*)&xs[cc][ty * 4];
            float4 b0 = *(const float4*)&ws[cc][tx * 8];
            float4 b1 = *(const float4*)&ws[cc][tx * 8 + 4];
            float a[4]  = {av.x, av.y, av.z, av.w};
            float bb[8] = {b0.x, b0.y, b0.z, b0.w, b1.x, b1.y, b1.z, b1.w};
#pragma unroll
            for (int i = 0; i < 4; i++)
#pragma unroll
                for (int j = 0; j < 8; j++)
                    acc[i][j] = fmaf(a[i], bb[j], acc[i][j]);
        }
        __syncthreads();
    }

    // epilogue: add summed biases and store
    const int gb = g0 + tx * 8;
    float4 b1a = *(const float4*)(wb + S1OFF + gb);
    float4 b1b = *(const float4*)(wb + S1OFF + gb + 4);
    float4 b2a = *(const float4*)(wb + S1OFF + Gn + gb);
    float4 b2b = *(const float4*)(wb + S1OFF + Gn + gb + 4);
    float bias[8] = {b1a.x + b2a.x, b1a.y + b2a.y, b1a.z + b2a.z, b1a.w + b2a.w,
                     b1b.x + b2b.x, b1b.y + b2b.y, b1b.z + b2b.z, b1b.w + b2b.w};

    float* og = g_xg + (size_t)b * (Ln * (size_t)Gn);
#pragma unroll
    for (int i = 0; i < 4; i++) {
        int l = l0 + ty * 4 + i;
        float4 o0, o1;
        o0.x = acc[i][0] + bias[0]; o0.y = acc[i][1] + bias[1];
        o0.z = acc[i][2] + bias[2]; o0.w = acc[i][3] + bias[3];
        o1.x = acc[i][4] + bias[4]; o1.y = acc[i][5] + bias[5];
        o1.z = acc[i][6] + bias[6]; o1.w = acc[i][7] + bias[7];
        *(float4*)(og + (size_t)l * Gn + gb)     = o0;
        *(float4*)(og + (size_t)l * Gn + gb + 4) = o1;
    }
}

// ---------------------------------------------------------------------------
// Kernel 3: the sequential LSTM scan. One CTA per batch (64 CTAs), 512
// threads, 2 gates per thread. Weights streamed from L2 (W_t is resident:
// 64 MB < 126 MB L2; xg/y use streaming cache hints to protect residency).
// ---------------------------------------------------------------------------
__global__ void __launch_bounds__(512) scan_kernel(const float* __restrict__ state,
                                                   float* __restrict__ out) {
    __shared__ float h_s[Hn];
    __shared__ float c_s[Hn];
    __shared__ float gate_s[Gn];

    const int b   = blockIdx.x;
    const int tid = threadIdx.x;

    if (tid < Hn) {
        h_s[tid] = state[b * 2 * Hn + tid];
        c_s[tid] = state[b * 2 * Hn + Hn + tid];
    }
    __syncthreads();

    // float2 views: thread owns gates (2*tid, 2*tid+1)
    const float2* Wp  = (const float2*)(g_wt + (size_t)b * (Hn * (size_t)Gn)) + tid;
    const float2* xgp = (const float2*)(g_xg + (size_t)b * (Ln * (size_t)Gn)) + tid;
    float* yb = out + (size_t)b * (Hn * (size_t)Ln);

#pragma unroll 1
    for (int t = 0; t < Ln; t++) {
        // xg load overlaps the whole k-loop (added at the end)
        float2 xv = __ldcs(xgp + (size_t)t * (Gn / 2));
        float acc0 = 0.f, acc1 = 0.f;

#pragma unroll 1
        for (int k0 = 0; k0 < Hn; k0 += 16) {
            float2 wv[16];
#pragma unroll
            for (int u = 0; u < 16; u++)
                wv[u] = __ldg(Wp + (size_t)(k0 + u) * (Gn / 2));
#pragma unroll
            for (int u = 0; u < 16; u++) {
                float hk = h_s[k0 + u];
                acc0 = fmaf(wv[u].x, hk, acc0);
                acc1 = fmaf(wv[u].y, hk, acc1);
            }
        }

        gate_s[2 * tid]     = acc0 + xv.x;
        gate_s[2 * tid + 1] = acc1 + xv.y;
        __syncthreads();

        if (tid < Hn) {
            float ig = fast_sigmoid(gate_s[tid]);
            float fg = fast_sigmoid(gate_s[Hn + tid]);
            float gg = fast_tanh(gate_s[2 * Hn + tid]);
            float og = fast_sigmoid(gate_s[3 * Hn + tid]);
            float c  = fmaf(fg, c_s[tid], ig * gg);
            float h  = og * fast_tanh(c);
            c_s[tid] = c;
            h_s[tid] = h;
            __stcs(yb + (size_t)tid * Ln + t, h);
        }
        __syncthreads();
    }

    if (tid < Hn) {
        size_t so = (size_t)Bn * Hn * Ln + (size_t)b * 2 * Hn;
        out[so + tid]      = h_s[tid];
        out[so + Hn + tid] = c_s[tid];
    }
}

// ---------------------------------------------------------------------------
// Launch
// ---------------------------------------------------------------------------
extern "C" void kernel_launch(void* const* d_in, const int* in_sizes, int n_in,
                              void* d_out, int out_size) {
    // Identify inputs by element count (robust to ordering)
    const float* x  = nullptr;   // 64*128*1024  = 8,388,608
    const float* st = nullptr;   // 64*512       = 32,768
    const float* w  = nullptr;   // 64*395264    = 25,296,896
    for (int i = 0; i < n_in; i++) {
        int n = in_sizes[i];
        if (n == Bn * Cn * Ln)        x  = (const float*)d_in[i];
        else if (n == Bn * 2 * Hn)    st = (const float*)d_in[i];
        else if (n == Bn * WSTRIDE)   w  = (const float*)d_in[i];
    }
    float* out = (float*)d_out;
    (void)out_size;

    transpose_whh_kernel<<<dim3(Hn / 32, Gn / 32, Bn), dim3(32, 8)>>>(w);
    gemm_xg_kernel<<<dim3(Gn / TG, Ln / TL, Bn), 256>>>(x, w);
    scan_kernel<<<Bn, 512>>>(st, out);
}

// round 17
// speedup vs baseline: 2.7507x; 2.7507x over previous
#include <cuda_runtime.h>
#include <cuda_fp16.h>
#include <cstddef>
#include <cstdint>

// Problem constants
#define Bn 64
#define Cn 128
#define Hn 256
#define Ln 1024
#define Gn 1024                    // 4*H
#define WSTRIDE 395264             // 4*H*(C+H+2)
#define S0OFF 131072               // G*C
#define S1OFF 393216               // S0 + G*H
#define KS 216                     // k-rows resident in SMEM (fp16); tail 40 rows from L2

// Scratch (device-global; no runtime allocation allowed)
__device__ float  g_xg[(size_t)Bn * Ln * Gn];              // [b][l][g]   268 MB
__device__ __half g_wp[(size_t)Bn * 2 * 256 * 512];        // packed recurrent weights 33.5 MB
// Packed layout (per cta, in __half units):
//   pair p = k>>1 (128 pairs), gate-pair j = gl>>1 (256), idx =
//   p*1024 + j*4 + (k&1)*2 + (gl&1)
// => one uint2 (8B) per thread yields w[k][2j..2j+1] and w[k+1][2j..2j+1].

// ---------------------------------------------------------------------------
// Fast nonlinearities (tanh.approx: abs err ~1e-5, far below 1e-3 tolerance)
// ---------------------------------------------------------------------------
__device__ __forceinline__ float fast_tanh(float x) {
    float r;
    asm("tanh.approx.f32 %0, %1;" : "=f"(r) : "f"(x));
    return r;
}
__device__ __forceinline__ float fast_sigmoid(float x) {
    return fmaf(fast_tanh(0.5f * x), 0.5f, 0.5f);
}

// ---------------------------------------------------------------------------
// Kernel 1: pack W_hh[b][grow][k] (fp32) -> g_wp (fp16, paired layout above)
// cta = b*2 + r. Local gate gl = q*128 + j  <->  global row grow = q*256 + r*128 + j.
// ---------------------------------------------------------------------------
__global__ void __launch_bounds__(256) pack_whh_kernel(const float* __restrict__ w) {
    __shared__ float tile[32][33];
    const int cta = blockIdx.z;          // 0..127
    const int b   = cta >> 1;
    const int r   = cta & 1;
    const int k0  = blockIdx.x * 32;     // 256/32 = 8
    const int gl0 = blockIdx.y * 32;     // 512/32 = 16
    const int tx  = threadIdx.x;         // 32
    const int ty  = threadIdx.y;         // 8

    const float* src = w + (size_t)b * WSTRIDE + S0OFF;
#pragma unroll
    for (int i = 0; i < 4; i++) {
        int gl   = gl0 + ty + i * 8;
        int grow = (gl >> 7) * 256 + r * 128 + (gl & 127);
        tile[ty + i * 8][tx] = src[(size_t)grow * Hn + k0 + tx];
    }
    __syncthreads();
    __half* dst = g_wp + (size_t)cta * (256 * 512);
#pragma unroll
    for (int i = 0; i < 4; i++) {
        int k  = k0 + ty + i * 8;
        int gl = gl0 + tx;
        size_t idx = (size_t)(k >> 1) * 1024 + (gl >> 1) * 4 + (k & 1) * 2 + (gl & 1);
        dst[idx] = __float2half(tile[tx][ty + i * 8]);
    }
}

// ---------------------------------------------------------------------------
// Kernel 2: xg[b][l][g] = sum_c x[b][c][l] * W_ih[b][g][c] + bias1[g]+bias2[g]
// fp32 tiled GEMM: 64(l) x 128(g) per CTA, K=128 in chunks of 16. (R2-proven)
// ---------------------------------------------------------------------------
#define TL 64
#define TG 128
#define TC 16

__global__ void __launch_bounds__(256) gemm_xg_kernel(const float* __restrict__ x,
                                                      const float* __restrict__ w) {
    __shared__ float xs[TC][TL];
    __shared__ float ws[TC][TG + 8];

    const int b   = blockIdx.z;
    const int l0  = blockIdx.y * TL;
    const int g0  = blockIdx.x * TG;
    const int tid = threadIdx.x;
    const int tx  = tid & 15;
    const int ty  = tid >> 4;

    const float* xb = x + (size_t)b * (Cn * (size_t)Ln);
    const float* wb = w + (size_t)b * WSTRIDE;

    float acc[4][8];
#pragma unroll
    for (int i = 0; i < 4; i++)
#pragma unroll
        for (int j = 0; j < 8; j++) acc[i][j] = 0.f;

    const int xr = tid >> 4;
    const int xc = (tid & 15) * 4;

    for (int c0 = 0; c0 < Cn; c0 += TC) {
        float4 xv = *(const float4*)(xb + (size_t)(c0 + xr) * Ln + l0 + xc);
        *(float4*)&xs[xr][xc] = xv;
#pragma unroll
        for (int it = 0; it < 2; it++) {
            int fi = tid + it * 256;
            int g  = fi >> 2;
            int cq = (fi & 3) * 4;
            float4 wv = *(const float4*)(wb + (size_t)(g0 + g) * Cn + c0 + cq);
            ws[cq + 0][g] = wv.x;
            ws[cq + 1][g] = wv.y;
            ws[cq + 2][g] = wv.z;
            ws[cq + 3][g] = wv.w;
        }
        __syncthreads();
#pragma unroll
        for (int cc = 0; cc < TC; cc++) {
            float4 av = *(const float4*)&xs[cc][ty * 4];
            float4 b0 = *(const float4*)&ws[cc][tx * 8];
            float4 b1 = *(const float4*)&ws[cc][tx * 8 + 4];
            float a[4]  = {av.x, av.y, av.z, av.w};
            float bb[8] = {b0.x, b0.y, b0.z, b0.w, b1.x, b1.y, b1.z, b1.w};
#pragma unroll
            for (int i = 0; i < 4; i++)
#pragma unroll
                for (int j = 0; j < 8; j++)
                    acc[i][j] = fmaf(a[i], bb[j], acc[i][j]);
        }
        __syncthreads();
    }

    const int gb = g0 + tx * 8;
    float4 b1a = *(const float4*)(wb + S1OFF + gb);
    float4 b1b = *(const float4*)(wb + S1OFF + gb + 4);
    float4 b2a = *(const float4*)(wb + S1OFF + Gn + gb);
    float4 b2b = *(const float4*)(wb + S1OFF + Gn + gb + 4);
    float bias[8] = {b1a.x + b2a.x, b1a.y + b2a.y, b1a.z + b2a.z, b1a.w + b2a.w,
                     b1b.x + b2b.x, b1b.y + b2b.y, b1b.z + b2b.z, b1b.w + b2b.w};

    float* og = g_xg + (size_t)b * (Ln * (size_t)Gn);
#pragma unroll
    for (int i = 0; i < 4; i++) {
        int l = l0 + ty * 4 + i;
        float4 o0, o1;
        o0.x = acc[i][0] + bias[0]; o0.y = acc[i][1] + bias[1];
        o0.z = acc[i][2] + bias[2]; o0.w = acc[i][3] + bias[3];
        o1.x = acc[i][4] + bias[4]; o1.y = acc[i][5] + bias[5];
        o1.z = acc[i][6] + bias[6]; o1.w = acc[i][7] + bias[7];
        *(float4*)(og + (size_t)l * Gn + gb)     = o0;
        *(float4*)(og + (size_t)l * Gn + gb + 4) = o1;
    }
}

// ---------------------------------------------------------------------------
// Kernel 3: LSTM scan. Cluster of 2 CTAs per batch (128 CTAs, 1/SM).
// Each CTA owns 128 h-indices (512 gate rows). fp16 weights: 216 k-rows in
// SMEM (216 KB), 40-row tail streamed from L2-resident g_wp. Per-step h
// exchange via DSMEM into a double-buffered h array; one cluster barrier/step.
// Paired layout => one LDS.64/LDG.64 fetches 2 k-rows per thread.
// ---------------------------------------------------------------------------
extern __shared__ __half ws_dyn[];   // first KS/2 pairs, contiguous (KS*512 halves)

__global__ void __cluster_dims__(2, 1, 1) __launch_bounds__(256, 1)
scan_kernel(const float* __restrict__ state, float* __restrict__ out) {
    __shared__ __align__(16) float h_s[2][256];
    __shared__ float c_s[128];
    __shared__ float gbuf[512];

    const int cta = blockIdx.x;
    const int b   = cta >> 1;
    const int r   = cta & 1;
    const int tid = threadIdx.x;

    const __half* wsrc = g_wp + (size_t)cta * (256 * 512);

    // Prologue: stage first KS rows (= KS/2 pairs, contiguous) into SMEM
    {
        const uint4* s4 = (const uint4*)wsrc;
        uint4*       d4 = (uint4*)ws_dyn;
#pragma unroll 4
        for (int i = tid; i < KS * 512 / 8; i += 256) d4[i] = s4[i];
    }
    h_s[0][tid] = state[b * 2 * Hn + tid];
    if (tid < 128) c_s[tid] = state[b * 2 * Hn + Hn + r * 128 + tid];
    __syncthreads();

    // Peer SMEM address of h_s for DSMEM stores
    uint32_t h_local = (uint32_t)__cvta_generic_to_shared(&h_s[0][0]);
    uint32_t h_peer;
    asm("mapa.shared::cluster.u32 %0, %1, %2;" : "=r"(h_peer) : "r"(h_local), "r"(r ^ 1));

    asm volatile("barrier.cluster.arrive.aligned;" ::: "memory");
    asm volatile("barrier.cluster.wait.aligned;"   ::: "memory");

    // uint2 views: pair p occupies uint2 indices [p*256, (p+1)*256)
    const uint2* __restrict__ wsu = (const uint2*)ws_dyn;
    const uint2* __restrict__ wtu = (const uint2*)wsrc + (KS / 2) * 256 + tid;

    // xg mapping: thread owns local gates gl=2*tid, 2*tid+1
    const int q     = tid >> 6;                 // (2*tid) >> 7
    const int jj    = (2 * tid) & 127;
    const int grow0 = q * 256 + r * 128 + jj;   // global gate row (even)
    const float2* __restrict__ xgp = (const float2*)(g_xg + (size_t)b * Ln * Gn) + (grow0 >> 1);

    float* __restrict__ yb = out + (size_t)b * (Hn * (size_t)Ln);

#pragma unroll 1
    for (int t = 0; t < Ln; t++) {
        const int cur = t & 1;
        const float* hb = h_s[cur];

        // xg load issued early (streams from DRAM/L2; latency covered by matvec)
        float2 xv = __ldcs(xgp + (size_t)t * (Gn / 2));

        float acc0 = 0.f, acc1 = 0.f;

        // Tail rows from L2 first (front-batched LDG.64, MLP=4, hides latency)
#pragma unroll 1
        for (int k = KS; k < 256; k += 8) {
            uint2 uv[4];
#pragma unroll
            for (int u = 0; u < 4; u++)
                uv[u] = __ldg(wtu + (size_t)(((k - KS) >> 1) + u) * 256);
#pragma unroll
            for (int u = 0; u < 4; u++) {
                float2 wa  = __half22float2(*(const half2*)&uv[u].x);  // row k+2u
                float2 wb2 = __half22float2(*(const half2*)&uv[u].y);  // row k+2u+1
                float h0 = hb[k + 2 * u];
                float h1 = hb[k + 2 * u + 1];
                acc0 = fmaf(wa.x,  h0, acc0); acc1 = fmaf(wa.y,  h0, acc1);
                acc0 = fmaf(wb2.x, h1, acc0); acc1 = fmaf(wb2.y, h1, acc1);
            }
        }

        // SMEM-resident rows: 4 LDS.64 per 8 k-rows
#pragma unroll 1
        for (int k0 = 0; k0 < KS; k0 += 8) {
            float4 ha = *(const float4*)(hb + k0);
            float4 hc = *(const float4*)(hb + k0 + 4);
            const int p0 = k0 >> 1;
            uint2 u0 = wsu[(p0 + 0) * 256 + tid];
            uint2 u1 = wsu[(p0 + 1) * 256 + tid];
            uint2 u2 = wsu[(p0 + 2) * 256 + tid];
            uint2 u3 = wsu[(p0 + 3) * 256 + tid];
            float2 f0 = __half22float2(*(const half2*)&u0.x);
            float2 f1 = __half22float2(*(const half2*)&u0.y);
            float2 f2 = __half22float2(*(const half2*)&u1.x);
            float2 f3 = __half22float2(*(const half2*)&u1.y);
            float2 f4 = __half22float2(*(const half2*)&u2.x);
            float2 f5 = __half22float2(*(const half2*)&u2.y);
            float2 f6 = __half22float2(*(const half2*)&u3.x);
            float2 f7 = __half22float2(*(const half2*)&u3.y);
            acc0 = fmaf(f0.x, ha.x, acc0); acc1 = fmaf(f0.y, ha.x, acc1);
            acc0 = fmaf(f1.x, ha.y, acc0); acc1 = fmaf(f1.y, ha.y, acc1);
            acc0 = fmaf(f2.x, ha.z, acc0); acc1 = fmaf(f2.y, ha.z, acc1);
            acc0 = fmaf(f3.x, ha.w, acc0); acc1 = fmaf(f3.y, ha.w, acc1);
            acc0 = fmaf(f4.x, hc.x, acc0); acc1 = fmaf(f4.y, hc.x, acc1);
            acc0 = fmaf(f5.x, hc.y, acc0); acc1 = fmaf(f5.y, hc.y, acc1);
            acc0 = fmaf(f6.x, hc.z, acc0); acc1 = fmaf(f6.y, hc.z, acc1);
            acc0 = fmaf(f7.x, hc.w, acc0); acc1 = fmaf(f7.y, hc.w, acc1);
        }

        gbuf[2 * tid]     = acc0 + xv.x;
        gbuf[2 * tid + 1] = acc1 + xv.y;
        __syncthreads();

        if (tid < 128) {
            float ig = fast_sigmoid(gbuf[tid]);
            float fg = fast_sigmoid(gbuf[128 + tid]);
            float gg = fast_tanh(gbuf[256 + tid]);
            float og = fast_sigmoid(gbuf[384 + tid]);
            float c  = fmaf(fg, c_s[tid], ig * gg);
            float h  = og * fast_tanh(c);
            c_s[tid] = c;
            const int hidx = r * 128 + tid;
            const int nxt  = cur ^ 1;
            h_s[nxt][hidx] = h;
            asm volatile("st.shared::cluster.f32 [%0], %1;"
                         :: "r"(h_peer + (uint32_t)((nxt * 256 + hidx) * 4)), "f"(h));
            __stcs(yb + (size_t)hidx * Ln + t, h);
        }
        // One cluster barrier per step: releases our DSMEM h-writes, acquires
        // the peer's, and doubles as the CTA barrier protecting gbuf/h reuse.
        asm volatile("barrier.cluster.arrive.aligned;" ::: "memory");
        asm volatile("barrier.cluster.wait.aligned;"   ::: "memory");
    }

    if (tid < 128) {
        const size_t so  = (size_t)Bn * Hn * Ln + (size_t)b * 2 * Hn;
        const int   hidx = r * 128 + tid;
        out[so + hidx]      = h_s[0][hidx];   // after t=1023 (odd), final h is in buffer 0
        out[so + Hn + hidx] = c_s[tid];
    }
}

// ---------------------------------------------------------------------------
// Launch
// ---------------------------------------------------------------------------
extern "C" void kernel_launch(void* const* d_in, const int* in_sizes, int n_in,
                              void* d_out, int out_size) {
    const float* x  = nullptr;
    const float* st = nullptr;
    const float* w  = nullptr;
    for (int i = 0; i < n_in; i++) {
        int n = in_sizes[i];
        if (n == Bn * Cn * Ln)       x  = (const float*)d_in[i];
        else if (n == Bn * 2 * Hn)   st = (const float*)d_in[i];
        else if (n == Bn * WSTRIDE)  w  = (const float*)d_in[i];
    }
    float* out = (float*)d_out;
    (void)out_size;

    // Raise dynamic SMEM cap for the scan (host-side attribute; not an allocation)
    cudaFuncSetAttribute(scan_kernel, cudaFuncAttributeMaxDynamicSharedMemorySize,
                         KS * 512 * 2);

    pack_whh_kernel<<<dim3(8, 16, Bn * 2), dim3(32, 8)>>>(w);
    gemm_xg_kernel<<<dim3(Gn / TG, Ln / TL, Bn), 256>>>(x, w);
    scan_kernel<<<Bn * 2, 256, KS * 512 * 2>>>(st, out);
}